// round 7
// baseline (speedup 1.0000x reference)
#include <cuda_runtime.h>
#include <cuda_bf16.h>

#define BB 64
#define SS 576
#define DD 768
#define CC 200
#define NPAD 208     // padded class dim (26 * 8)
#define MT 64        // s-rows per CTA  (576 = 9 * 64, exact)
#define KC 32        // K chunk
#define APAD 34      // smem row stride in bf16 elems (32 + 2 pad)

// bf16 copy of attn_w, zero-padded to NPAD rows. Static device scratch (no allocs).
__device__ __nv_bfloat16 g_wbf[NPAD * DD];

__device__ __forceinline__ float sigf(float x) {
    return 1.f / (1.f + __expf(-x));
}

// ---------------------------------------------------------------------------
// Kernel 0: convert attn_w (200x768 f32) -> g_wbf (208x768 bf16, rows >=200 zero)
// ---------------------------------------------------------------------------
__global__ void convert_w_kernel(const float* __restrict__ w) {
    int idx = blockIdx.x * 256 + threadIdx.x;
    if (idx >= NPAD * DD) return;
    int c = idx / DD;
    float v = (c < CC) ? w[idx] : 0.f;   // for c<CC, idx == c*DD+d is the valid index
    g_wbf[idx] = __float2bfloat16(v);
}

// ---------------------------------------------------------------------------
// Kernel 1: global_scores = class_token @ gc_w^T + gc_b  (fp32, writes out)
// grid (64, 25), block 256 : one warp per (b, c)
// ---------------------------------------------------------------------------
__global__ void global_scores_kernel(const float* __restrict__ ct,
                                     const float* __restrict__ gcw,
                                     const float* __restrict__ gcb,
                                     float* __restrict__ out) {
    int b = blockIdx.x;
    int warp = threadIdx.x >> 5;
    int lane = threadIdx.x & 31;
    int c = blockIdx.y * 8 + warp;          // 25*8 = 200 exactly
    const float* x = ct + (size_t)b * DD;
    const float* w = gcw + (size_t)c * DD;
    float acc = 0.f;
    #pragma unroll 4
    for (int d = lane; d < DD; d += 32) acc += x[d] * w[d];
    #pragma unroll
    for (int m = 16; m; m >>= 1) acc += __shfl_xor_sync(0xffffffffu, acc, m);
    if (lane == 0) out[b * CC + c] = acc + gcb[c];
}

// ---------------------------------------------------------------------------
// Kernel 2: fused  logits = patch @ attn_w^T ; att = sigmoid(logits + b);
//           out[b,c] += lam/(S*D) * sum_s att[b,c,s] * rowsum[b,s]
// CTA tile: M=64 (s) x N=208 (c), K loop over 768 in chunks of 32.
// 8 warps as 4(m) x 2(n); warp tile 16 x 104 = 13 n-frags of m16n8k16.
// Register-staged global->smem double buffering (f32 -> bf16 convert on store),
// rowsum accumulated during the A stores.
// ---------------------------------------------------------------------------
__global__ void __launch_bounds__(256, 2)
attn_kernel(const float* __restrict__ patch,
            const float* __restrict__ attn_b,
            const float* __restrict__ lam,
            float* __restrict__ out) {
    __shared__ __nv_bfloat16 As[MT][APAD];
    __shared__ __nv_bfloat16 Bs[NPAD][APAD];
    __shared__ float rs[MT];
    __shared__ float colsum[NPAD];

    const int tid  = threadIdx.x;
    const int lane = tid & 31;
    const int warp = tid >> 5;
    const int wm   = warp >> 1;          // 0..3
    const int wn   = warp & 1;           // 0..1
    const int g    = lane >> 2;          // 0..7
    const int q    = lane & 3;           // 0..3

    const int b  = blockIdx.y;
    const int s0 = blockIdx.x * MT;

    if (tid < NPAD) colsum[tid] = 0.f;

    const float* pA = patch + ((size_t)b * SS + s0) * DD;

    float acc[13][4];
    #pragma unroll
    for (int j = 0; j < 13; ++j) {
        acc[j][0] = 0.f; acc[j][1] = 0.f; acc[j][2] = 0.f; acc[j][3] = 0.f;
    }

    // staging registers
    float4 areg[2];
    uint4  breg[4];
    float rsum0 = 0.f, rsum1 = 0.f;

    const int ar0 = tid >> 3;            // A row (i=0); i=1 -> +32
    const int ac  = (tid & 7) * 4;       // A col (f32 elems)

    auto loadT = [&](int kt) {
        const int k0 = kt * KC;
        areg[0] = *reinterpret_cast<const float4*>(pA + (size_t)ar0 * DD + k0 + ac);
        areg[1] = *reinterpret_cast<const float4*>(pA + (size_t)(ar0 + 32) * DD + k0 + ac);
        #pragma unroll
        for (int i = 0; i < 4; ++i) {
            int f = tid + 256 * i;                       // 16B chunk id, 832 total
            if (f < 832) {
                int row = f >> 2;                        // 0..207
                int c8  = (f & 3) * 8;                   // bf16 col
                breg[i] = *reinterpret_cast<const uint4*>(g_wbf + (size_t)row * DD + k0 + c8);
            }
        }
    };

    auto storeT = [&]() {
        #pragma unroll
        for (int i = 0; i < 2; ++i) {
            float4 v = areg[i];
            int row = ar0 + 32 * i;
            *reinterpret_cast<__nv_bfloat162*>(&As[row][ac])     = __floats2bfloat162_rn(v.x, v.y);
            *reinterpret_cast<__nv_bfloat162*>(&As[row][ac + 2]) = __floats2bfloat162_rn(v.z, v.w);
            float s = v.x + v.y + v.z + v.w;
            if (i == 0) rsum0 += s; else rsum1 += s;
        }
        #pragma unroll
        for (int i = 0; i < 4; ++i) {
            int f = tid + 256 * i;
            if (f < 832) {
                int row = f >> 2;
                int c8  = (f & 3) * 8;
                uint4 v = breg[i];
                *reinterpret_cast<unsigned*>(&Bs[row][c8])     = v.x;
                *reinterpret_cast<unsigned*>(&Bs[row][c8 + 2]) = v.y;
                *reinterpret_cast<unsigned*>(&Bs[row][c8 + 4]) = v.z;
                *reinterpret_cast<unsigned*>(&Bs[row][c8 + 6]) = v.w;
            }
        }
    };

    loadT(0);
    for (int kt = 0; kt < DD / KC; ++kt) {
        storeT();
        __syncthreads();
        if (kt < DD / KC - 1) loadT(kt + 1);     // LDGs in flight during compute

        #pragma unroll
        for (int h = 0; h < 2; ++h) {            // two k16 steps per KC=32
            const int k0 = h * 16;
            const int ra = wm * 16 + g;
            unsigned a0 = *reinterpret_cast<const unsigned*>(&As[ra    ][k0 + 2 * q]);
            unsigned a1 = *reinterpret_cast<const unsigned*>(&As[ra + 8][k0 + 2 * q]);
            unsigned a2 = *reinterpret_cast<const unsigned*>(&As[ra    ][k0 + 2 * q + 8]);
            unsigned a3 = *reinterpret_cast<const unsigned*>(&As[ra + 8][k0 + 2 * q + 8]);
            #pragma unroll
            for (int j = 0; j < 13; ++j) {
                const int cb = wn * 104 + j * 8 + g;
                unsigned b0 = *reinterpret_cast<const unsigned*>(&Bs[cb][k0 + 2 * q]);
                unsigned b1 = *reinterpret_cast<const unsigned*>(&Bs[cb][k0 + 2 * q + 8]);
                asm volatile(
                    "mma.sync.aligned.m16n8k16.row.col.f32.bf16.bf16.f32 "
                    "{%0,%1,%2,%3},{%4,%5,%6,%7},{%8,%9},{%0,%1,%2,%3};\n"
                    : "+f"(acc[j][0]), "+f"(acc[j][1]), "+f"(acc[j][2]), "+f"(acc[j][3])
                    : "r"(a0), "r"(a1), "r"(a2), "r"(a3), "r"(b0), "r"(b1));
            }
        }
        __syncthreads();
    }

    // ---- rowsum reduce: 8 threads per row (same octet) ----
    #pragma unroll
    for (int m = 1; m < 8; m <<= 1) {
        rsum0 += __shfl_xor_sync(0xffffffffu, rsum0, m);
        rsum1 += __shfl_xor_sync(0xffffffffu, rsum1, m);
    }
    if ((lane & 7) == 0) {
        int row = tid >> 3;
        rs[row]      = rsum0;
        rs[row + 32] = rsum1;
    }
    __syncthreads();

    // ---- epilogue: sigmoid(logit + bias) * rowsum, reduce over s ----
    const float rlo = rs[wm * 16 + g];
    const float rhi = rs[wm * 16 + g + 8];
    #pragma unroll
    for (int j = 0; j < 13; ++j) {
        const int ce = wn * 104 + j * 8 + 2 * q;
        float be = (ce     < CC) ? __ldg(&attn_b[ce])     : 0.f;
        float bo = (ce + 1 < CC) ? __ldg(&attn_b[ce + 1]) : 0.f;
        float pe = sigf(acc[j][0] + be) * rlo + sigf(acc[j][2] + be) * rhi;
        float po = sigf(acc[j][1] + bo) * rlo + sigf(acc[j][3] + bo) * rhi;
        #pragma unroll
        for (int m = 4; m < 32; m <<= 1) {
            pe += __shfl_xor_sync(0xffffffffu, pe, m);
            po += __shfl_xor_sync(0xffffffffu, po, m);
        }
        if (lane < 4) {   // lane == q for the reduced group
            atomicAdd(&colsum[ce],     pe);
            atomicAdd(&colsum[ce + 1], po);
        }
    }
    __syncthreads();

    if (tid < CC) {
        float scale = __ldg(&lam[0]) * (1.f / (float)(SS * DD));
        atomicAdd(&out[b * CC + tid], scale * colsum[tid]);
    }
}

// ---------------------------------------------------------------------------
// kernel_launch: inputs per metadata order:
// 0 patch_tokens (64,576,768) f32 | 1 class_token (64,768) | 2 attn_w (200,768)
// 3 attn_b (200) | 4 gc_w (200,768) | 5 gc_b (200) | 6 lam (1)
// out: (64,200) f32
// ---------------------------------------------------------------------------
extern "C" void kernel_launch(void* const* d_in, const int* in_sizes, int n_in,
                              void* d_out, int out_size) {
    (void)in_sizes; (void)n_in; (void)out_size;
    const float* patch = (const float*)d_in[0];
    const float* ct    = (const float*)d_in[1];
    const float* aw    = (const float*)d_in[2];
    const float* ab    = (const float*)d_in[3];
    const float* gw    = (const float*)d_in[4];
    const float* gb    = (const float*)d_in[5];
    const float* lam   = (const float*)d_in[6];
    float* out = (float*)d_out;

    convert_w_kernel<<<(NPAD * DD + 255) / 256, 256>>>(aw);
    global_scores_kernel<<<dim3(BB, CC / 8), 256>>>(ct, gw, gb, out);
    attn_kernel<<<dim3(SS / MT, BB), 256>>>(patch, ab, lam, out);
}

// round 10
// speedup vs baseline: 1.2663x; 1.2663x over previous
#include <cuda_runtime.h>
#include <cuda_fp16.h>
#include <cstdint>

#define BB 64
#define SS 576
#define DD 768
#define CC 200
#define NP 208             // padded class dim
#define MT 64              // s-rows per CTA (576 = 9*64)
#define KC 32              // K chunk (elems)
#define NK 24              // 768/32
#define NSTAGE 3

#define AF32_STRIDE 36     // f32 elems per A stage row (144 B, conflict-free)
#define AH_STRIDE   40     // f16 elems per row (80 B, LDSM conflict-free)
#define BH_STRIDE   40

#define OFF_AF32 0
#define SZ_AF32  (NSTAGE * MT * AF32_STRIDE * 4)        // 27648
#define OFF_AH   (OFF_AF32 + SZ_AF32)
#define SZ_AH    (MT * AH_STRIDE * 2)                   // 5120
#define OFF_BH   (OFF_AH + SZ_AH)                       // 32768
#define SZ_BH    (NSTAGE * NP * BH_STRIDE * 2)          // 49920
#define OFF_RS   (OFF_BH + SZ_BH)                       // 82688
#define OFF_CS   (OFF_RS + MT * 4)                      // 82944
#define SMEM_TOTAL (OFF_CS + NP * 4)                    // 83776

// fp16 copy of attn_w, zero-padded to NP rows (static scratch, no allocs)
__device__ __half g_whf[NP * DD];

__device__ __forceinline__ uint32_t smem_u32(const void* p) {
    uint32_t a;
    asm("{ .reg .u64 t; cvta.to.shared.u64 t, %1; cvt.u32.u64 %0, t; }" : "=r"(a) : "l"(p));
    return a;
}
__device__ __forceinline__ void cp_async16(uint32_t dst, const void* src) {
    asm volatile("{ .reg .u64 g; cvta.to.global.u64 g, %1; cp.async.cg.shared.global [%0], [g], 16; }"
                 :: "r"(dst), "l"(src) : "memory");
}
#define CP_COMMIT() asm volatile("cp.async.commit_group;" ::: "memory")
#define CP_WAIT1()  asm volatile("cp.async.wait_group 1;" ::: "memory")

#define LDSM4(r0, r1, r2, r3, addr)                                           \
    asm volatile("ldmatrix.sync.aligned.m8n8.x4.shared.b16 {%0,%1,%2,%3}, [%4];" \
        : "=r"(r0), "=r"(r1), "=r"(r2), "=r"(r3) : "r"(addr))
#define LDSM2(r0, r1, addr)                                                   \
    asm volatile("ldmatrix.sync.aligned.m8n8.x2.shared.b16 {%0,%1}, [%2];"    \
        : "=r"(r0), "=r"(r1) : "r"(addr))

#define MMA16(c0, c1, a0, a1, a2, a3, b0, b1)                                 \
    asm volatile("mma.sync.aligned.m16n8k16.row.col.f16.f16.f16.f16 "         \
        "{%0,%1},{%2,%3,%4,%5},{%6,%7},{%0,%1};"                              \
        : "+r"(c0), "+r"(c1)                                                  \
        : "r"(a0), "r"(a1), "r"(a2), "r"(a3), "r"(b0), "r"(b1))

__device__ __forceinline__ float sigf(float x) { return 1.f / (1.f + __expf(-x)); }

// ---------------------------------------------------------------------------
// prep kernel: blocks [0,78): convert attn_w -> g_whf (f16, zero-padded rows)
//              blocks [78,1678): global_scores = class_token @ gc_w^T + gc_b
// ---------------------------------------------------------------------------
__global__ void prep_kernel(const float* __restrict__ aw,
                            const float* __restrict__ ct,
                            const float* __restrict__ gcw,
                            const float* __restrict__ gcb,
                            float* __restrict__ out) {
    int bid = blockIdx.x;
    if (bid < 78) {
        int base = bid * 2048 + threadIdx.x * 8;   // 78*2048 = 159744 = NP*DD
        #pragma unroll
        for (int i = 0; i < 8; ++i) {
            int idx = base + i;
            int c = idx / DD;
            float v = (c < CC) ? aw[idx] : 0.f;
            g_whf[idx] = __float2half(v);
        }
    } else {
        int W = (bid - 78) * 8 + (threadIdx.x >> 5);   // 0..12799
        int lane = threadIdx.x & 31;
        int b = W & 63;
        int c = W >> 6;                                // 0..199
        const float* x = ct + (size_t)b * DD;
        const float* w = gcw + (size_t)c * DD;
        float acc = 0.f;
        #pragma unroll 4
        for (int d = lane; d < DD; d += 32) acc += x[d] * w[d];
        #pragma unroll
        for (int m = 16; m; m >>= 1) acc += __shfl_xor_sync(0xffffffffu, acc, m);
        if (lane == 0) out[b * CC + c] = acc + gcb[c];
    }
}

// ---------------------------------------------------------------------------
// attn kernel: fused logits = patch @ attn_w^T (f16 mma.sync, cp.async pipe),
//   out[b,c] += lam/(S*D) * sum_s sigmoid(logit + bias) * rowsum[b,s]
// CTA tile M=64 x N=208; 8 warps 4(m) x 2(n); warp tile 16 x 104.
// ---------------------------------------------------------------------------
__global__ void __launch_bounds__(256, 2)
attn_kernel(const float* __restrict__ patch,
            const float* __restrict__ attn_b,
            const float* __restrict__ lam,
            float* __restrict__ out) {
    extern __shared__ __align__(16) char smem[];
    float*  Af = (float*)(smem + OFF_AF32);
    __half* Ah = (__half*)(smem + OFF_AH);
    float*  rs = (float*)(smem + OFF_RS);
    float*  colsum = (float*)(smem + OFF_CS);
    const uint32_t sb = smem_u32(smem);

    const int tid  = threadIdx.x;
    const int lane = tid & 31;
    const int warp = tid >> 5;
    const int wm   = warp >> 1;          // 0..3
    const int wn   = warp & 1;           // 0..1
    const int g    = lane >> 2;          // 0..7
    const int q    = lane & 3;           // 0..3

    const int b  = blockIdx.y;
    const int s0 = blockIdx.x * MT;

    if (tid < NP) colsum[tid] = 0.f;

    const float* gA = patch + ((size_t)b * SS + s0) * DD;

    // ldmatrix per-lane byte offsets (conflict-free via 80B row strides)
    const uint32_t aoff = (uint32_t)(((lane & 7) + ((lane >> 3) & 1) * 8) * (AH_STRIDE * 2)
                                     + ((lane >> 4) & 1) * 16);
    const uint32_t boff = (uint32_t)(((lane & 7) + ((lane >> 4) & 1) * 8) * (BH_STRIDE * 2)
                                     + ((lane >> 3) & 1) * 16);
    const uint32_t abase = sb + OFF_AH + wm * 16 * (AH_STRIDE * 2) + aoff;

    uint32_t acc[13][2];
    #pragma unroll
    for (int j = 0; j < 13; ++j) { acc[j][0] = 0u; acc[j][1] = 0u; }
    float rsum = 0.f;

    auto issue = [&](int kt) {
        const int st = kt % NSTAGE;
        uint32_t adst = sb + OFF_AF32 + st * (MT * AF32_STRIDE * 4);
        #pragma unroll
        for (int i = 0; i < 2; ++i) {                   // 512 A chunks of 16B
            int c = tid + 256 * i;
            int row = c >> 3, cc = c & 7;
            cp_async16(adst + row * (AF32_STRIDE * 4) + cc * 16,
                       gA + (size_t)row * DD + kt * KC + cc * 4);
        }
        uint32_t bdst = sb + OFF_BH + st * (NP * BH_STRIDE * 2);
        #pragma unroll
        for (int i = 0; i < 4; ++i) {                   // 832 B chunks of 16B
            int f = tid + 256 * i;
            if (f < NP * 4) {
                int row = f >> 2, cc = f & 3;
                cp_async16(bdst + row * (BH_STRIDE * 2) + cc * 16,
                           g_whf + (size_t)row * DD + kt * KC + cc * 8);
            }
        }
        CP_COMMIT();
    };

    issue(0);
    issue(1);

    const int crow = tid >> 2;           // convert: 4 threads per row
    const int cseg = tid & 3;            // 8 f32 each

    for (int kt = 0; kt < NK; ++kt) {
        const int st = kt % NSTAGE;
        CP_WAIT1();
        __syncthreads();                 // stage st arrived; prev compute done

        if (kt + 2 < NK) issue(kt + 2); else CP_COMMIT();

        // ---- convert A f32 -> f16 + rowsum partial ----
        {
            const float* ap = Af + st * (MT * AF32_STRIDE) + crow * AF32_STRIDE + cseg * 8;
            float4 x = *reinterpret_cast<const float4*>(ap);
            float4 y = *reinterpret_cast<const float4*>(ap + 4);
            rsum += (x.x + x.y) + (x.z + x.w) + (y.x + y.y) + (y.z + y.w);
            __half2 h0 = __floats2half2_rn(x.x, x.y);
            __half2 h1 = __floats2half2_rn(x.z, x.w);
            __half2 h2 = __floats2half2_rn(y.x, y.y);
            __half2 h3 = __floats2half2_rn(y.z, y.w);
            uint4 u;
            u.x = *reinterpret_cast<uint32_t*>(&h0);
            u.y = *reinterpret_cast<uint32_t*>(&h1);
            u.z = *reinterpret_cast<uint32_t*>(&h2);
            u.w = *reinterpret_cast<uint32_t*>(&h3);
            *reinterpret_cast<uint4*>(Ah + crow * AH_STRIDE + cseg * 8) = u;
        }
        __syncthreads();                 // Ah visible to all warps

        // ---- mma: 2 k16 halves ----
        const uint32_t bstage = sb + OFF_BH + st * (NP * BH_STRIDE * 2)
                              + wn * 104 * (BH_STRIDE * 2) + boff;
        #pragma unroll
        for (int h = 0; h < 2; ++h) {
            uint32_t a0, a1, a2, a3;
            LDSM4(a0, a1, a2, a3, abase + h * 32);
            #pragma unroll
            for (int p = 0; p < 6; ++p) {
                uint32_t b0, b1, b2, b3;
                LDSM4(b0, b1, b2, b3, bstage + p * 16 * (BH_STRIDE * 2) + h * 32);
                MMA16(acc[2 * p][0],     acc[2 * p][1],     a0, a1, a2, a3, b0, b1);
                MMA16(acc[2 * p + 1][0], acc[2 * p + 1][1], a0, a1, a2, a3, b2, b3);
            }
            uint32_t b0, b1;
            LDSM2(b0, b1, bstage + 96 * (BH_STRIDE * 2) + h * 32);
            MMA16(acc[12][0], acc[12][1], a0, a1, a2, a3, b0, b1);
        }
    }

    // ---- rowsum reduce over the 4 threads per row ----
    rsum += __shfl_xor_sync(0xffffffffu, rsum, 1);
    rsum += __shfl_xor_sync(0xffffffffu, rsum, 2);
    if ((tid & 3) == 0) rs[crow] = rsum;
    __syncthreads();

    // ---- epilogue: sigmoid(logit + bias) * rowsum, reduce over s ----
    const float rlo = rs[wm * 16 + g];
    const float rhi = rs[wm * 16 + g + 8];
    #pragma unroll
    for (int j = 0; j < 13; ++j) {
        const int ce = wn * 104 + j * 8 + 2 * q;
        float2 c0 = __half22float2(*reinterpret_cast<__half2*>(&acc[j][0]));  // rows g
        float2 c1 = __half22float2(*reinterpret_cast<__half2*>(&acc[j][1]));  // rows g+8
        float be = (ce     < CC) ? __ldg(&attn_b[ce])     : 0.f;
        float bo = (ce + 1 < CC) ? __ldg(&attn_b[ce + 1]) : 0.f;
        float pe = sigf(c0.x + be) * rlo + sigf(c1.x + be) * rhi;
        float po = sigf(c0.y + bo) * rlo + sigf(c1.y + bo) * rhi;
        #pragma unroll
        for (int m = 4; m < 32; m <<= 1) {
            pe += __shfl_xor_sync(0xffffffffu, pe, m);
            po += __shfl_xor_sync(0xffffffffu, po, m);
        }
        if (lane < 4) {                  // lane == q
            atomicAdd(&colsum[ce],     pe);
            atomicAdd(&colsum[ce + 1], po);
        }
    }
    __syncthreads();

    if (tid < CC) {
        float scale = __ldg(&lam[0]) * (1.f / (float)(SS * DD));
        atomicAdd(&out[b * CC + tid], scale * colsum[tid]);
    }
}

// ---------------------------------------------------------------------------
// kernel_launch
// inputs: 0 patch (64,576,768) f32 | 1 class_token (64,768) | 2 attn_w (200,768)
//         3 attn_b (200) | 4 gc_w (200,768) | 5 gc_b (200) | 6 lam (1)
// out: (64,200) f32
// ---------------------------------------------------------------------------
extern "C" void kernel_launch(void* const* d_in, const int* in_sizes, int n_in,
                              void* d_out, int out_size) {
    (void)in_sizes; (void)n_in; (void)out_size;
    const float* patch = (const float*)d_in[0];
    const float* ct    = (const float*)d_in[1];
    const float* aw    = (const float*)d_in[2];
    const float* ab    = (const float*)d_in[3];
    const float* gw    = (const float*)d_in[4];
    const float* gb    = (const float*)d_in[5];
    const float* lam   = (const float*)d_in[6];
    float* out = (float*)d_out;

    cudaFuncSetAttribute(attn_kernel, cudaFuncAttributeMaxDynamicSharedMemorySize,
                         SMEM_TOTAL);

    prep_kernel<<<78 + 1600, 256>>>(aw, ct, gw, gb, out);
    attn_kernel<<<dim3(SS / MT, BB), 256, SMEM_TOTAL>>>(patch, ab, lam, out);
}